// round 4
// baseline (speedup 1.0000x reference)
#include <cuda_runtime.h>
#include <cuda_bf16.h>

typedef unsigned long long u64;

// Problem constants
constexpr int B  = 4096;
constexpr int T  = 200;
constexpr int F  = 36;
constexpr int H1 = 16;
constexpr int H2 = 32;
constexpr int H3 = 16;

constexpr int GRP     = 16;               // lanes cooperating on a batch quad
constexpr int NB      = 4;                // batches per thread (weight reuse)
constexpr int THREADS = 128;
constexpr int GROUPS  = THREADS / GRP;    // 8 groups per block
constexpr int BPB     = GROUPS * NB;      // 32 batches per block
constexpr int GRID    = B / BPB;          // 128 blocks

// ---------------------------------------------------------------------------
// Skewed, row-pair-interleaved weight layout.
// Lane k owns rows { q*H + (U*k + uu) }, flattened m = q*U+uu (0..4U-1).
// Row pair p = m>>1, slot = m&1; pair elements interleaved so one LDS.128
// (2 weights x 2 rows) feeds 2 FFMA2 per batch. laneStride mod 32 = odd*4
// -> 8 distinct 16B bank groups across lanes.
// ---------------------------------------------------------------------------
template<int H, int IN> struct LL {
    static constexpr int U = H / GRP;                 // units per lane (1 or 2)
    static constexpr int P = (4 * U) / 2;             // row pairs per lane
    static constexpr int whOff = P * 2 * IN;          // Wh section (floats)
    static constexpr int laneStride = P * 2 * (IN + H) + 4;
    static constexpr int blockFloats = GRP * laneStride;
};
using LY1 = LL<H1, F>;    // U=1 P=2 stride 212
using LY2 = LL<H2, H1>;   // U=2 P=4 stride 388
using LY3 = LL<H3, H2>;   // U=1 P=2 stride 196

constexpr int OFF_L1 = 0;
constexpr int OFF_L2 = OFF_L1 + LY1::blockFloats;
constexpr int OFF_L3 = OFF_L2 + LY2::blockFloats;
constexpr int OFF_B1 = OFF_L3 + LY3::blockFloats;
constexpr int OFF_B2 = OFF_B1 + 4 * H1;
constexpr int OFF_B3 = OFF_B2 + 4 * H2;
constexpr int SMEM_FLOATS = OFF_B3 + 4 * H3;
constexpr int SMEM_BYTES  = SMEM_FLOATS * 4;          // ~52 KB

__device__ float g_Wc[6 * 16];
__device__ float g_bc[6];

// ---- packed f32x2 helpers ----
__device__ __forceinline__ void fma2(u64 &acc, u64 w, u64 x) {
    asm("fma.rn.f32x2 %0, %1, %2, %0;" : "+l"(acc) : "l"(w), "l"(x));
}
__device__ __forceinline__ u64 pk(float v) {
    u64 r; asm("mov.b64 %0, {%1, %1};" : "=l"(r) : "f"(v)); return r;
}
__device__ __forceinline__ void upk(u64 v, float &lo, float &hi) {
    asm("mov.b64 {%0, %1}, %2;" : "=f"(lo), "=f"(hi) : "l"(v));
}
__device__ __forceinline__ float sigf(float x) {
    return __fdividef(1.0f, 1.0f + __expf(-x));
}
__device__ __forceinline__ float tanh_(float x) {
    return __fdividef(2.0f, 1.0f + __expf(-2.0f * x)) - 1.0f;
}

// ---- input getters ----
// Layer 1: stream x from gmem (16-lane broadcast via L1; 8B vector loads).
struct XGm {
    const float* p0; const float* p1; const float* p2; const float* p3;
    __device__ __forceinline__ void operator()(int j, float2 (&v)[NB]) const {
        v[0] = __ldg(reinterpret_cast<const float2*>(p0 + j));
        v[1] = __ldg(reinterpret_cast<const float2*>(p1 + j));
        v[2] = __ldg(reinterpret_cast<const float2*>(p2 + j));
        v[3] = __ldg(reinterpret_cast<const float2*>(p3 + j));
    }
};
// Layers 2/3 input + all recurrent paths: fetch h[j] from owner lane via shfl.
template<int U> struct XHs {
    const float (&h)[NB][U];
    __device__ __forceinline__ void operator()(int j, float2 (&v)[NB]) const {
        #pragma unroll
        for (int n = 0; n < NB; n++) {
            v[n].x = __shfl_sync(0xffffffffu, h[n][j % U], j / U, GRP);
            v[n].y = __shfl_sync(0xffffffffu, h[n][(j + 1) % U], (j + 1) / U, GRP);
        }
    }
};

// ---- one LSTM layer step, NB batches sharing every weight load ----
template<int H, int IN, typename GX>
__device__ __forceinline__ void lstm_core(
    const float* __restrict__ laneW, const u64* __restrict__ laneB,
    GX gx, float (&hown)[NB][H / GRP], float (&c)[NB][H / GRP])
{
    using L = LL<H, IN>;
    constexpr int U = L::U, P = L::P;

    u64 acc[NB][P];
    #pragma unroll
    for (int p = 0; p < P; p++) {
        u64 bv = laneB[p];
        #pragma unroll
        for (int n = 0; n < NB; n++) acc[n][p] = bv;
    }

    // input projection
    #pragma unroll
    for (int j = 0; j < IN; j += 2) {
        float2 xv[NB];
        gx(j, xv);
        u64 x0[NB], x1[NB];
        #pragma unroll
        for (int n = 0; n < NB; n++) { x0[n] = pk(xv[n].x); x1[n] = pk(xv[n].y); }
        #pragma unroll
        for (int p = 0; p < P; p++) {
            ulonglong2 w = *reinterpret_cast<const ulonglong2*>(laneW + p * 2 * IN + 2 * j);
            #pragma unroll
            for (int n = 0; n < NB; n++) {
                fma2(acc[n][p], w.x, x0[n]);
                fma2(acc[n][p], w.y, x1[n]);
            }
        }
    }

    // recurrent projection (reads previous h via shfl from owner lanes)
    XHs<U> hr{hown};
    #pragma unroll
    for (int j = 0; j < H; j += 2) {
        float2 xv[NB];
        hr(j, xv);
        u64 x0[NB], x1[NB];
        #pragma unroll
        for (int n = 0; n < NB; n++) { x0[n] = pk(xv[n].x); x1[n] = pk(xv[n].y); }
        #pragma unroll
        for (int p = 0; p < P; p++) {
            ulonglong2 w = *reinterpret_cast<const ulonglong2*>(laneW + L::whOff + p * 2 * H + 2 * j);
            #pragma unroll
            for (int n = 0; n < NB; n++) {
                fma2(acc[n][p], w.x, x0[n]);
                fma2(acc[n][p], w.y, x1[n]);
            }
        }
    }

    // gates + state update (all recurrent shfl reads done -> safe to overwrite)
    #pragma unroll
    for (int n = 0; n < NB; n++) {
        float ga[4 * U];
        #pragma unroll
        for (int p = 0; p < P; p++)
            upk(acc[n][p], ga[2 * p], ga[2 * p + 1]);
        #pragma unroll
        for (int u = 0; u < U; u++) {
            float ig = sigf(ga[0 * U + u]);
            float fg = sigf(ga[1 * U + u]);
            float gg = tanh_(ga[2 * U + u]);
            float og = sigf(ga[3 * U + u]);
            float cc = fmaf(fg, c[n][u], ig * gg);
            c[n][u] = cc;
            hown[n][u] = og * tanh_(cc);
        }
    }
}

// ---- staging: repack global weights into skewed interleaved layout ----
template<int H, int IN>
__device__ void stage(float* base, float* biasBase,
                      const float* __restrict__ Wx, const float* __restrict__ Wh,
                      const float* __restrict__ bih, const float* __restrict__ bhh,
                      int tid)
{
    using L = LL<H, IN>;
    for (int idx = tid; idx < 4 * H * IN; idx += THREADS) {
        int r = idx / IN, j = idx - r * IN;
        int q = r / H,    mr = r - q * H;
        int k = mr / L::U, uu = mr - k * L::U;
        int m = q * L::U + uu, p = m >> 1, slot = m & 1;
        base[k * L::laneStride + p * 2 * IN + 2 * j + slot] = Wx[idx];
    }
    for (int idx = tid; idx < 4 * H * H; idx += THREADS) {
        int r = idx / H,  j = idx - r * H;
        int q = r / H,    mr = r - q * H;
        int k = mr / L::U, uu = mr - k * L::U;
        int m = q * L::U + uu, p = m >> 1, slot = m & 1;
        base[k * L::laneStride + L::whOff + p * 2 * H + 2 * j + slot] = Wh[idx];
    }
    for (int r = tid; r < 4 * H; r += THREADS) {
        int q = r / H,    mr = r - q * H;
        int k = mr / L::U, uu = mr - k * L::U;
        int m = q * L::U + uu, p = m >> 1, slot = m & 1;
        biasBase[(k * L::P + p) * 2 + slot] = bih[r] + bhh[r];
    }
}

__global__ void __launch_bounds__(THREADS, 1) lstm_fused(
    const float* __restrict__ x,
    const float* __restrict__ Wih1, const float* __restrict__ Whh1,
    const float* __restrict__ bih1, const float* __restrict__ bhh1,
    const float* __restrict__ Wih2, const float* __restrict__ Whh2,
    const float* __restrict__ bih2, const float* __restrict__ bhh2,
    const float* __restrict__ Wih3, const float* __restrict__ Whh3,
    const float* __restrict__ bih3, const float* __restrict__ bhh3,
    float* __restrict__ out)
{
    extern __shared__ float sm[];
    const int tid = threadIdx.x;

    stage<H1, F >(sm + OFF_L1, sm + OFF_B1, Wih1, Whh1, bih1, bhh1, tid);
    stage<H2, H1>(sm + OFF_L2, sm + OFF_B2, Wih2, Whh2, bih2, bhh2, tid);
    stage<H3, H2>(sm + OFF_L3, sm + OFF_B3, Wih3, Whh3, bih3, bhh3, tid);
    __syncthreads();

    const int k  = tid & (GRP - 1);           // lane in group
    const int g  = tid >> 4;                  // group 0..7
    const int b0 = blockIdx.x * BPB + g * NB; // first of 4 batches

    const float* laneW1 = sm + OFF_L1 + k * LY1::laneStride;
    const float* laneW2 = sm + OFF_L2 + k * LY2::laneStride;
    const float* laneW3 = sm + OFF_L3 + k * LY3::laneStride;
    const u64* laneB1 = reinterpret_cast<const u64*>(sm + OFF_B1) + k * LY1::P;
    const u64* laneB2 = reinterpret_cast<const u64*>(sm + OFF_B2) + k * LY2::P;
    const u64* laneB3 = reinterpret_cast<const u64*>(sm + OFF_B3) + k * LY3::P;

    float h1[NB][LY1::U], h2[NB][LY2::U], h3[NB][LY3::U];
    float c1[NB][LY1::U], c2[NB][LY2::U], c3[NB][LY3::U];
    #pragma unroll
    for (int n = 0; n < NB; n++) {
        #pragma unroll
        for (int u = 0; u < LY1::U; u++) { h1[n][u] = 0.0f; c1[n][u] = 0.0f; }
        #pragma unroll
        for (int u = 0; u < LY2::U; u++) { h2[n][u] = 0.0f; c2[n][u] = 0.0f; }
        #pragma unroll
        for (int u = 0; u < LY3::U; u++) { h3[n][u] = 0.0f; c3[n][u] = 0.0f; }
    }

    const float* xb0 = x + (size_t)(b0 + 0) * T * F;
    const float* xb1 = x + (size_t)(b0 + 1) * T * F;
    const float* xb2 = x + (size_t)(b0 + 2) * T * F;
    const float* xb3 = x + (size_t)(b0 + 3) * T * F;

    for (int t = 0; t < T; t++) {
        XGm gx{xb0 + t * F, xb1 + t * F, xb2 + t * F, xb3 + t * F};
        lstm_core<H1, F >(laneW1, laneB1, gx,              h1, c1);
        lstm_core<H2, H1>(laneW2, laneB2, XHs<LY1::U>{h1}, h2, c2);
        lstm_core<H3, H2>(laneW3, laneB3, XHs<LY2::U>{h2}, h3, c3);
    }

    // collapsed head: gather h3 (U3=1 -> value lives in lane j), lanes 0..5 emit
    #pragma unroll
    for (int n = 0; n < NB; n++) {
        float hh[H3];
        #pragma unroll
        for (int j = 0; j < H3; j++)
            hh[j] = __shfl_sync(0xffffffffu, h3[n][0], j, GRP);
        if (k < 6) {
            float acc = g_bc[k];
            #pragma unroll
            for (int u = 0; u < H3; u++)
                acc = fmaf(hh[u], g_Wc[k * H3 + u], acc);
            out[(size_t)(b0 + n) * 6 + k] = acc;
        }
    }
}

// Collapse the 3 linear head layers into Wc [6,16], bc [6].
__global__ void head_precompute(
    const float* __restrict__ Wfc1, const float* __restrict__ bfc1,
    const float* __restrict__ Wfc2, const float* __restrict__ bfc2,
    const float* __restrict__ Wcls, const float* __restrict__ bcls)
{
    __shared__ float tmp[6 * 128];
    const int tid = threadIdx.x;

    for (int idx = tid; idx < 6 * 128; idx += blockDim.x) {
        int j = idx / 128, p = idx % 128;
        float s = 0.0f;
        for (int q = 0; q < 32; q++)
            s += Wcls[j * 32 + q] * Wfc2[q * 128 + p];
        tmp[idx] = s;
    }
    __syncthreads();

    for (int idx = tid; idx < 6 * 16; idx += blockDim.x) {
        int j = idx / 16, u = idx % 16;
        float s = 0.0f;
        for (int p = 0; p < 128; p++)
            s += tmp[j * 128 + p] * Wfc1[p * 16 + u];
        g_Wc[idx] = s;
    }
    if (tid < 6) {
        float s = bcls[tid];
        for (int q = 0; q < 32; q++)
            s += Wcls[tid * 32 + q] * bfc2[q];
        for (int p = 0; p < 128; p++)
            s += tmp[tid * 128 + p] * bfc1[p];
        g_bc[tid] = s;
    }
}

extern "C" void kernel_launch(void* const* d_in, const int* in_sizes, int n_in,
                              void* d_out, int out_size)
{
    (void)in_sizes; (void)n_in; (void)out_size;
    const float* x    = (const float*)d_in[0];
    const float* Wih1 = (const float*)d_in[1];
    const float* Whh1 = (const float*)d_in[2];
    const float* bih1 = (const float*)d_in[3];
    const float* bhh1 = (const float*)d_in[4];
    const float* Wih2 = (const float*)d_in[5];
    const float* Whh2 = (const float*)d_in[6];
    const float* bih2 = (const float*)d_in[7];
    const float* bhh2 = (const float*)d_in[8];
    const float* Wih3 = (const float*)d_in[9];
    const float* Whh3 = (const float*)d_in[10];
    const float* bih3 = (const float*)d_in[11];
    const float* bhh3 = (const float*)d_in[12];
    const float* Wfc1 = (const float*)d_in[13];
    const float* bfc1 = (const float*)d_in[14];
    const float* Wfc2 = (const float*)d_in[15];
    const float* bfc2 = (const float*)d_in[16];
    const float* Wcls = (const float*)d_in[17];
    const float* bcls = (const float*)d_in[18];
    float* out = (float*)d_out;

    static bool attr_set = false;
    if (!attr_set) {
        cudaFuncSetAttribute(lstm_fused,
                             cudaFuncAttributeMaxDynamicSharedMemorySize,
                             SMEM_BYTES);
        attr_set = true;
    }

    head_precompute<<<1, 256>>>(Wfc1, bfc1, Wfc2, bfc2, Wcls, bcls);
    lstm_fused<<<GRID, THREADS, SMEM_BYTES>>>(
        x, Wih1, Whh1, bih1, bhh1, Wih2, Whh2, bih2, bhh2,
        Wih3, Whh3, bih3, bhh3, out);
}

// round 5
// speedup vs baseline: 1.2130x; 1.2130x over previous
#include <cuda_runtime.h>
#include <cuda_bf16.h>

typedef unsigned long long u64;

constexpr int B = 4096, T = 200, F = 36;
constexpr int THREADS = 256, WARPS = 8, NBW = 4;   // 4 batches per warp
constexpr int BPB  = WARPS * NBW;                  // 32
constexpr int GRID = B / BPB;                      // 128

// Weight layout (floats). Per lane-block: 4 rows (=2 pairs), element-interleaved
// so one LDS.128 = 2 cols x 2 rows feeds 2 FFMA2. +4 skew per lane block.
constexpr int W1_STRIDE = 212, W2_STRIDE = 196, W3_STRIDE = 196;
constexpr int W1_WHOFF  = 144, W2_WHOFF  = 64,  W3_WHOFF  = 128;
constexpr int OFF_W1 = 0;
constexpr int OFF_W2 = OFF_W1 + 16 * W1_STRIDE;    // 3392
constexpr int OFF_W3 = OFF_W2 + 32 * W2_STRIDE;    // 9664
constexpr int OFF_B1 = OFF_W3 + 16 * W3_STRIDE;    // 12800
constexpr int OFF_B2 = OFF_B1 + 64;                // 12864
constexpr int OFF_B3 = OFF_B2 + 128;               // 12992
constexpr int OFF_H  = OFF_B3 + 64;                // 13056 (16B aligned)

// Per-warp h region (u64 = duplicated f32x2). Padded strides for bank spread.
constexpr int H1_STR = 18, H2_STR = 34, H3_STR = 18;   // u64 per batch-row
constexpr int HW_H1 = 0, HW_H2 = 4 * H1_STR, HW_H3 = HW_H2 + 4 * H2_STR;
constexpr int HW_TOTAL = HW_H3 + 4 * H3_STR;           // 280 u64 per warp
constexpr int SMEM_FLOATS = OFF_H + WARPS * HW_TOTAL * 2;
constexpr int SMEM_BYTES  = SMEM_FLOATS * 4;           // ~70 KB

__device__ float g_Wc[6 * 16];
__device__ float g_bc[6];

__device__ __forceinline__ void fma2(u64 &acc, u64 w, u64 x) {
    asm("fma.rn.f32x2 %0, %1, %2, %0;" : "+l"(acc) : "l"(w), "l"(x));
}
__device__ __forceinline__ u64 pk(float v) {
    u64 r; asm("mov.b64 %0, {%1, %1};" : "=l"(r) : "f"(v)); return r;
}
__device__ __forceinline__ void upk(u64 v, float &lo, float &hi) {
    asm("mov.b64 {%0, %1}, %2;" : "=f"(lo), "=f"(hi) : "l"(v));
}
__device__ __forceinline__ float sigf(float x) {
    return __fdividef(1.0f, 1.0f + __expf(-x));
}
__device__ __forceinline__ float tanh_(float x) {
    return __fdividef(2.0f, 1.0f + __expf(-2.0f * x)) - 1.0f;
}

__global__ void __launch_bounds__(THREADS, 1) lstm_fused(
    const float* __restrict__ x,
    const float* __restrict__ Wih1, const float* __restrict__ Whh1,
    const float* __restrict__ bih1, const float* __restrict__ bhh1,
    const float* __restrict__ Wih2, const float* __restrict__ Whh2,
    const float* __restrict__ bih2, const float* __restrict__ bhh2,
    const float* __restrict__ Wih3, const float* __restrict__ Whh3,
    const float* __restrict__ bih3, const float* __restrict__ bhh3,
    float* __restrict__ out)
{
    extern __shared__ float sm[];
    const int tid = threadIdx.x;

    // ---- stage weights into skewed interleaved layout ----
    // L1: 64 rows x 36 (GRP=16 blocks)
    for (int idx = tid; idx < 64 * 36; idx += THREADS) {
        int r = idx / 36, j = idx - r * 36;
        int q = r >> 4, un = r & 15, p = q >> 1, s = q & 1;
        sm[OFF_W1 + un * W1_STRIDE + p * 72 + 2 * j + s] = Wih1[idx];
    }
    for (int idx = tid; idx < 64 * 16; idx += THREADS) {
        int r = idx >> 4, j = idx & 15;
        int q = r >> 4, un = r & 15, p = q >> 1, s = q & 1;
        sm[OFF_W1 + un * W1_STRIDE + W1_WHOFF + p * 32 + 2 * j + s] = Whh1[idx];
    }
    for (int r = tid; r < 64; r += THREADS) {
        int q = r >> 4, un = r & 15, p = q >> 1, s = q & 1;
        sm[OFF_B1 + (un * 2 + p) * 2 + s] = bih1[r] + bhh1[r];
    }
    // L2: 128 rows x 16 (Wx) / x 32 (Wh), GRP=32 blocks
    for (int idx = tid; idx < 128 * 16; idx += THREADS) {
        int r = idx >> 4, j = idx & 15;
        int q = r >> 5, un = r & 31, p = q >> 1, s = q & 1;
        sm[OFF_W2 + un * W2_STRIDE + p * 32 + 2 * j + s] = Wih2[idx];
    }
    for (int idx = tid; idx < 128 * 32; idx += THREADS) {
        int r = idx >> 5, j = idx & 31;
        int q = r >> 5, un = r & 31, p = q >> 1, s = q & 1;
        sm[OFF_W2 + un * W2_STRIDE + W2_WHOFF + p * 64 + 2 * j + s] = Whh2[idx];
    }
    for (int r = tid; r < 128; r += THREADS) {
        int q = r >> 5, un = r & 31, p = q >> 1, s = q & 1;
        sm[OFF_B2 + (un * 2 + p) * 2 + s] = bih2[r] + bhh2[r];
    }
    // L3: 64 rows x 32 (Wx) / x 16 (Wh), GRP=16 blocks
    for (int idx = tid; idx < 64 * 32; idx += THREADS) {
        int r = idx >> 5, j = idx & 31;
        int q = r >> 4, un = r & 15, p = q >> 1, s = q & 1;
        sm[OFF_W3 + un * W3_STRIDE + p * 64 + 2 * j + s] = Wih3[idx];
    }
    for (int idx = tid; idx < 64 * 16; idx += THREADS) {
        int r = idx >> 4, j = idx & 15;
        int q = r >> 4, un = r & 15, p = q >> 1, s = q & 1;
        sm[OFF_W3 + un * W3_STRIDE + W3_WHOFF + p * 32 + 2 * j + s] = Whh3[idx];
    }
    for (int r = tid; r < 64; r += THREADS) {
        int q = r >> 4, un = r & 15, p = q >> 1, s = q & 1;
        sm[OFF_B3 + (un * 2 + p) * 2 + s] = bih3[r] + bhh3[r];
    }
    // zero h region
    for (int i = tid; i < WARPS * HW_TOTAL * 2; i += THREADS)
        sm[OFF_H + i] = 0.0f;
    __syncthreads();

    const int lane = tid & 31;
    const int w    = tid >> 5;
    const int half = lane >> 4;       // 0: batches 0,1   1: batches 2,3 (L1/L3)
    const int hl   = lane & 15;       // lane within half

    u64* hw  = reinterpret_cast<u64*>(sm + OFF_H) + w * HW_TOTAL;
    u64* h1u = hw + HW_H1;
    u64* h2u = hw + HW_H2;
    u64* h3u = hw + HW_H3;

    const float* w1 = sm + OFF_W1 + hl * W1_STRIDE;
    const float* w2 = sm + OFF_W2 + lane * W2_STRIDE;
    const float* w3 = sm + OFF_W3 + hl * W3_STRIDE;
    const u64* b1 = reinterpret_cast<const u64*>(sm + OFF_B1) + hl * 2;
    const u64* b2 = reinterpret_cast<const u64*>(sm + OFF_B2) + lane * 2;
    const u64* b3 = reinterpret_cast<const u64*>(sm + OFF_B3) + hl * 2;

    const int b0 = blockIdx.x * BPB + w * NBW;
    const float4* xr0 = reinterpret_cast<const float4*>(x + (size_t)(b0 + half * 2 + 0) * T * F);
    const float4* xr1 = reinterpret_cast<const float4*>(x + (size_t)(b0 + half * 2 + 1) * T * F);

    const u64* h1self = h1u + half * 2 * H1_STR;
    const u64* h2self = h2u + half * 2 * H2_STR;
    const u64* h3self = h3u + half * 2 * H3_STR;

    float c1[2] = {0.f, 0.f}, c3[2] = {0.f, 0.f};
    float c2[4] = {0.f, 0.f, 0.f, 0.f};

    for (int t = 0; t < T; t++) {
        // ================= Layer 1 (H=16, half-warp, 2 local batches) =======
        u64 a1[2][2];
        a1[0][0] = b1[0]; a1[0][1] = b1[1];
        a1[1][0] = b1[0]; a1[1][1] = b1[1];
        // input projection from gmem x
        #pragma unroll
        for (int q = 0; q < 9; q++) {
            float4 v0 = __ldg(xr0 + t * 9 + q);
            float4 v1 = __ldg(xr1 + t * 9 + q);
            u64 p00 = pk(v0.x), p01 = pk(v0.y), p02 = pk(v0.z), p03 = pk(v0.w);
            u64 p10 = pk(v1.x), p11 = pk(v1.y), p12 = pk(v1.z), p13 = pk(v1.w);
            #pragma unroll
            for (int p = 0; p < 2; p++) {
                ulonglong2 wa = *reinterpret_cast<const ulonglong2*>(w1 + p * 72 + 8 * q);
                ulonglong2 wb = *reinterpret_cast<const ulonglong2*>(w1 + p * 72 + 8 * q + 4);
                fma2(a1[0][p], wa.x, p00); fma2(a1[0][p], wa.y, p01);
                fma2(a1[0][p], wb.x, p02); fma2(a1[0][p], wb.y, p03);
                fma2(a1[1][p], wa.x, p10); fma2(a1[1][p], wa.y, p11);
                fma2(a1[1][p], wb.x, p12); fma2(a1[1][p], wb.y, p13);
            }
        }
        // recurrent projection
        #pragma unroll
        for (int j = 0; j < 16; j += 2) {
            ulonglong2 hx0 = *reinterpret_cast<const ulonglong2*>(h1self + 0 * H1_STR + j);
            ulonglong2 hx1 = *reinterpret_cast<const ulonglong2*>(h1self + 1 * H1_STR + j);
            #pragma unroll
            for (int p = 0; p < 2; p++) {
                ulonglong2 wv = *reinterpret_cast<const ulonglong2*>(w1 + W1_WHOFF + p * 32 + 2 * j);
                fma2(a1[0][p], wv.x, hx0.x); fma2(a1[0][p], wv.y, hx0.y);
                fma2(a1[1][p], wv.x, hx1.x); fma2(a1[1][p], wv.y, hx1.y);
            }
        }
        #pragma unroll
        for (int ln = 0; ln < 2; ln++) {
            float gi, gf, gg, go;
            upk(a1[ln][0], gi, gf);
            upk(a1[ln][1], gg, go);
            float cc = fmaf(sigf(gf), c1[ln], sigf(gi) * tanh_(gg));
            c1[ln] = cc;
            h1u[(half * 2 + ln) * H1_STR + hl] = pk(sigf(go) * tanh_(cc));
        }
        __syncwarp();

        // ================= Layer 2 (H=32, full warp, 4 batches) =============
        u64 a2[4][2];
        #pragma unroll
        for (int n = 0; n < 4; n++) { a2[n][0] = b2[0]; a2[n][1] = b2[1]; }
        #pragma unroll
        for (int j = 0; j < 16; j += 2) {
            ulonglong2 w0 = *reinterpret_cast<const ulonglong2*>(w2 + 2 * j);
            ulonglong2 w1v = *reinterpret_cast<const ulonglong2*>(w2 + 32 + 2 * j);
            #pragma unroll
            for (int n = 0; n < 4; n++) {
                ulonglong2 hx = *reinterpret_cast<const ulonglong2*>(h1u + n * H1_STR + j);
                fma2(a2[n][0], w0.x, hx.x);  fma2(a2[n][0], w0.y, hx.y);
                fma2(a2[n][1], w1v.x, hx.x); fma2(a2[n][1], w1v.y, hx.y);
            }
        }
        #pragma unroll
        for (int j = 0; j < 32; j += 2) {
            ulonglong2 w0 = *reinterpret_cast<const ulonglong2*>(w2 + W2_WHOFF + 2 * j);
            ulonglong2 w1v = *reinterpret_cast<const ulonglong2*>(w2 + W2_WHOFF + 64 + 2 * j);
            #pragma unroll
            for (int n = 0; n < 4; n++) {
                ulonglong2 hx = *reinterpret_cast<const ulonglong2*>(h2u + n * H2_STR + j);
                fma2(a2[n][0], w0.x, hx.x);  fma2(a2[n][0], w0.y, hx.y);
                fma2(a2[n][1], w1v.x, hx.x); fma2(a2[n][1], w1v.y, hx.y);
            }
        }
        #pragma unroll
        for (int n = 0; n < 4; n++) {
            float gi, gf, gg, go;
            upk(a2[n][0], gi, gf);
            upk(a2[n][1], gg, go);
            float cc = fmaf(sigf(gf), c2[n], sigf(gi) * tanh_(gg));
            c2[n] = cc;
            h2u[n * H2_STR + lane] = pk(sigf(go) * tanh_(cc));
        }
        __syncwarp();

        // ================= Layer 3 (H=16, half-warp, 2 local batches) =======
        u64 a3[2][2];
        a3[0][0] = b3[0]; a3[0][1] = b3[1];
        a3[1][0] = b3[0]; a3[1][1] = b3[1];
        #pragma unroll
        for (int j = 0; j < 32; j += 2) {
            ulonglong2 hx0 = *reinterpret_cast<const ulonglong2*>(h2self + 0 * H2_STR + j);
            ulonglong2 hx1 = *reinterpret_cast<const ulonglong2*>(h2self + 1 * H2_STR + j);
            #pragma unroll
            for (int p = 0; p < 2; p++) {
                ulonglong2 wv = *reinterpret_cast<const ulonglong2*>(w3 + p * 64 + 2 * j);
                fma2(a3[0][p], wv.x, hx0.x); fma2(a3[0][p], wv.y, hx0.y);
                fma2(a3[1][p], wv.x, hx1.x); fma2(a3[1][p], wv.y, hx1.y);
            }
        }
        #pragma unroll
        for (int j = 0; j < 16; j += 2) {
            ulonglong2 hx0 = *reinterpret_cast<const ulonglong2*>(h3self + 0 * H3_STR + j);
            ulonglong2 hx1 = *reinterpret_cast<const ulonglong2*>(h3self + 1 * H3_STR + j);
            #pragma unroll
            for (int p = 0; p < 2; p++) {
                ulonglong2 wv = *reinterpret_cast<const ulonglong2*>(w3 + W3_WHOFF + p * 32 + 2 * j);
                fma2(a3[0][p], wv.x, hx0.x); fma2(a3[0][p], wv.y, hx0.y);
                fma2(a3[1][p], wv.x, hx1.x); fma2(a3[1][p], wv.y, hx1.y);
            }
        }
        #pragma unroll
        for (int ln = 0; ln < 2; ln++) {
            float gi, gf, gg, go;
            upk(a3[ln][0], gi, gf);
            upk(a3[ln][1], gg, go);
            float cc = fmaf(sigf(gf), c3[ln], sigf(gi) * tanh_(gg));
            c3[ln] = cc;
            h3u[(half * 2 + ln) * H3_STR + hl] = pk(sigf(go) * tanh_(cc));
        }
        __syncwarp();
    }

    // ---- collapsed head: lane<24 -> (batch n, class) ----
    if (lane < 24) {
        int n = lane / 6, cls = lane - n * 6;
        const float* hrow = reinterpret_cast<const float*>(h3u + n * H3_STR);
        float acc = g_bc[cls];
        #pragma unroll
        for (int u = 0; u < 16; u++)
            acc = fmaf(hrow[2 * u], g_Wc[cls * 16 + u], acc);
        out[(size_t)(b0 + n) * 6 + cls] = acc;
    }
}

// Collapse the 3 linear head layers into Wc [6,16], bc [6].
__global__ void head_precompute(
    const float* __restrict__ Wfc1, const float* __restrict__ bfc1,
    const float* __restrict__ Wfc2, const float* __restrict__ bfc2,
    const float* __restrict__ Wcls, const float* __restrict__ bcls)
{
    __shared__ float tmp[6 * 128];
    const int tid = threadIdx.x;

    for (int idx = tid; idx < 6 * 128; idx += blockDim.x) {
        int j = idx / 128, p = idx % 128;
        float s = 0.0f;
        for (int q = 0; q < 32; q++)
            s += Wcls[j * 32 + q] * Wfc2[q * 128 + p];
        tmp[idx] = s;
    }
    __syncthreads();

    for (int idx = tid; idx < 6 * 16; idx += blockDim.x) {
        int j = idx / 16, u = idx % 16;
        float s = 0.0f;
        for (int p = 0; p < 128; p++)
            s += tmp[j * 128 + p] * Wfc1[p * 16 + u];
        g_Wc[idx] = s;
    }
    if (tid < 6) {
        float s = bcls[tid];
        for (int q = 0; q < 32; q++)
            s += Wcls[tid * 32 + q] * bfc2[q];
        for (int p = 0; p < 128; p++)
            s += tmp[tid * 128 + p] * bfc1[p];
        g_bc[tid] = s;
    }
}

extern "C" void kernel_launch(void* const* d_in, const int* in_sizes, int n_in,
                              void* d_out, int out_size)
{
    (void)in_sizes; (void)n_in; (void)out_size;
    const float* x    = (const float*)d_in[0];
    const float* Wih1 = (const float*)d_in[1];
    const float* Whh1 = (const float*)d_in[2];
    const float* bih1 = (const float*)d_in[3];
    const float* bhh1 = (const float*)d_in[4];
    const float* Wih2 = (const float*)d_in[5];
    const float* Whh2 = (const float*)d_in[6];
    const float* bih2 = (const float*)d_in[7];
    const float* bhh2 = (const float*)d_in[8];
    const float* Wih3 = (const float*)d_in[9];
    const float* Whh3 = (const float*)d_in[10];
    const float* bih3 = (const float*)d_in[11];
    const float* bhh3 = (const float*)d_in[12];
    const float* Wfc1 = (const float*)d_in[13];
    const float* bfc1 = (const float*)d_in[14];
    const float* Wfc2 = (const float*)d_in[15];
    const float* bfc2 = (const float*)d_in[16];
    const float* Wcls = (const float*)d_in[17];
    const float* bcls = (const float*)d_in[18];
    float* out = (float*)d_out;

    static bool attr_set = false;
    if (!attr_set) {
        cudaFuncSetAttribute(lstm_fused,
                             cudaFuncAttributeMaxDynamicSharedMemorySize,
                             SMEM_BYTES);
        attr_set = true;
    }

    head_precompute<<<1, 256>>>(Wfc1, bfc1, Wfc2, bfc2, Wcls, bcls);
    lstm_fused<<<GRID, THREADS, SMEM_BYTES>>>(
        x, Wih1, Whh1, bih1, bhh1, Wih2, Whh2, bih2, bhh2,
        Wih3, Whh3, bih3, bhh3, out);
}